// round 16
// baseline (speedup 1.0000x reference)
#include <cuda_runtime.h>

// 2-qubit dense gate on 24-qubit state, batch=4 (innermost, contiguous).
// Flat float index = qindex * 4 + b.  qubit k -> bit (23-k) of qindex.
// support (5,12) -> qindex bits 18 and 11.
//
// FINAL. R1 configuration — best timed draw (81.6us) among six
// configurations that all pin the DRAM mixed read/write turnaround
// ceiling (75.0-75.7us device, 6.36-6.41 TB/s = ~80% of 8TB/s spec).
// Session evidence: occupancy 62-85% flat; block 128~256>512; per-thread
// ILP (regs>32) regresses via occupancy; __ldcs/__stcs/smem-gate all
// neutral; L2 39% and issue 16% rule out on-chip limits; traffic
// irreducible (512 MiB, one touch per byte each way).

static constexpr unsigned REST_BITS = 22;          // 24 - 2 support qubits
static constexpr unsigned N_REST    = 1u << REST_BITS;
static constexpr unsigned BIT_C     = 1u << 18;    // qubit 5
static constexpr unsigned BIT_D     = 1u << 11;    // qubit 12

__global__ void __launch_bounds__(256)
quantum_gate2_kernel(const float4* __restrict__ in,
                     const float*  __restrict__ gate,
                     float4*       __restrict__ out)
{
    unsigned r = blockIdx.x * blockDim.x + threadIdx.x;
    // Expand rest index: insert zero bits at positions 11 and 18.
    unsigned low = r & 0x7FFu;           // bits 0..10
    unsigned mid = (r >> 11) & 0x3Fu;    // -> qindex bits 12..17
    unsigned hi  = r >> 17;              // -> qindex bits 19..23
    unsigned qb  = low | (mid << 12) | (hi << 19);

    // Load the 4 basis amplitudes (each a float4 across the batch).
    float4 v0 = in[qb];                  // c=0,d=0
    float4 v1 = in[qb | BIT_D];          // c=0,d=1
    float4 v2 = in[qb | BIT_C];          // c=1,d=0
    float4 v3 = in[qb | BIT_C | BIT_D];  // c=1,d=1

    // Gate: 16 floats, uniform broadcast load.
    float g[16];
#pragma unroll
    for (int i = 0; i < 16; i++) g[i] = __ldg(gate + i);

    float4 o[4];
#pragma unroll
    for (int i = 0; i < 4; i++) {
        o[i].x = g[4*i+0]*v0.x + g[4*i+1]*v1.x + g[4*i+2]*v2.x + g[4*i+3]*v3.x;
        o[i].y = g[4*i+0]*v0.y + g[4*i+1]*v1.y + g[4*i+2]*v2.y + g[4*i+3]*v3.y;
        o[i].z = g[4*i+0]*v0.z + g[4*i+1]*v1.z + g[4*i+2]*v2.z + g[4*i+3]*v3.z;
        o[i].w = g[4*i+0]*v0.w + g[4*i+1]*v1.w + g[4*i+2]*v2.w + g[4*i+3]*v3.w;
    }

    out[qb]                 = o[0];
    out[qb | BIT_D]         = o[1];
    out[qb | BIT_C]         = o[2];
    out[qb | BIT_C | BIT_D] = o[3];
}

extern "C" void kernel_launch(void* const* d_in, const int* in_sizes, int n_in,
                              void* d_out, int out_size)
{
    const float4* state = (const float4*)d_in[0];
    const float*  gate  = (const float*)d_in[1];
    float4*       out   = (float4*)d_out;

    const unsigned threads = 256;
    const unsigned blocks  = N_REST / threads;   // 2^22 / 256 = 16384
    quantum_gate2_kernel<<<blocks, threads>>>(state, gate, out);
}

// round 17
// speedup vs baseline: 1.0757x; 1.0757x over previous
#include <cuda_runtime.h>

// 2-qubit dense gate on 24-qubit state, batch=4 (innermost, contiguous).
// Flat float index = qindex * 4 + b.  qubit k -> bit (23-k) of qindex.
// support (5,12) -> qindex bits 18 and 11.
//
// FINAL — R5 configuration, the variance-robust optimum. Reproduced 3x
// at 75.0/75.2/75.7us device time, DRAM 80.3-80.9% (6.36-6.41 TB/s =
// ~80% of 8TB/s spec = the mixed read/write turnaround ceiling).
// R16 proved the alternative (R1: 39 regs, occ 61%, per-thread gate
// loads) is node-fragile: same source re-measured at 85.5us / 72% DRAM
// on a slower draw. This config's occ ~80% + minimal L1 traffic gives
// MLP headroom that absorbs node/DVFS variance.
// Session evidence: occupancy 62-85% flat on fast nodes; block sizes
// 128~256>512; per-thread ILP (regs>32) regresses via occupancy;
// __ldcs load hints neutral; L2 39% / issue 16% rule out on-chip
// limits; traffic irreducible (512 MiB, one touch per byte each way).

static constexpr unsigned REST_BITS = 22;          // 24 - 2 support qubits
static constexpr unsigned N_REST    = 1u << REST_BITS;
static constexpr unsigned BIT_C     = 1u << 18;    // qubit 5
static constexpr unsigned BIT_D     = 1u << 11;    // qubit 12

__global__ void __launch_bounds__(256, 8)
quantum_gate2_kernel(const float4* __restrict__ in,
                     const float*  __restrict__ gate,
                     float4*       __restrict__ out)
{
    __shared__ float gs[16];
    if (threadIdx.x < 16) gs[threadIdx.x] = gate[threadIdx.x];
    __syncthreads();

    const unsigned r = blockIdx.x * blockDim.x + threadIdx.x;
    // Expand rest index: insert zero bits at qindex positions 11 and 18.
    const unsigned low = r & 0x7FFu;           // bits 0..10
    const unsigned mid = (r >> 11) & 0x3Fu;    // -> qindex bits 12..17
    const unsigned hi  = r >> 17;              // -> qindex bits 19..23
    const unsigned qb  = low | (mid << 12) | (hi << 19);

    const float4* pin  = in  + qb;
    float4*       pout = out + qb;

    // Front-batch the 4 independent 16B loads (per-thread MLP=4).
    const float4 v0 = pin[0u];                // c=0,d=0
    const float4 v1 = pin[BIT_D];             // c=0,d=1
    const float4 v2 = pin[BIT_C];             // c=1,d=0
    const float4 v3 = pin[BIT_C + BIT_D];     // c=1,d=1

    float4 o;

    o.x = gs[0]*v0.x + gs[1]*v1.x + gs[2]*v2.x + gs[3]*v3.x;
    o.y = gs[0]*v0.y + gs[1]*v1.y + gs[2]*v2.y + gs[3]*v3.y;
    o.z = gs[0]*v0.z + gs[1]*v1.z + gs[2]*v2.z + gs[3]*v3.z;
    o.w = gs[0]*v0.w + gs[1]*v1.w + gs[2]*v2.w + gs[3]*v3.w;
    __stcs(pout, o);

    o.x = gs[4]*v0.x + gs[5]*v1.x + gs[6]*v2.x + gs[7]*v3.x;
    o.y = gs[4]*v0.y + gs[5]*v1.y + gs[6]*v2.y + gs[7]*v3.y;
    o.z = gs[4]*v0.z + gs[5]*v1.z + gs[6]*v2.z + gs[7]*v3.z;
    o.w = gs[4]*v0.w + gs[5]*v1.w + gs[6]*v2.w + gs[7]*v3.w;
    __stcs(pout + BIT_D, o);

    o.x = gs[8]*v0.x + gs[9]*v1.x + gs[10]*v2.x + gs[11]*v3.x;
    o.y = gs[8]*v0.y + gs[9]*v1.y + gs[10]*v2.y + gs[11]*v3.y;
    o.z = gs[8]*v0.z + gs[9]*v1.z + gs[10]*v2.z + gs[11]*v3.z;
    o.w = gs[8]*v0.w + gs[9]*v1.w + gs[10]*v2.w + gs[11]*v3.w;
    __stcs(pout + BIT_C, o);

    o.x = gs[12]*v0.x + gs[13]*v1.x + gs[14]*v2.x + gs[15]*v3.x;
    o.y = gs[12]*v0.y + gs[13]*v1.y + gs[14]*v2.y + gs[15]*v3.y;
    o.z = gs[12]*v0.z + gs[13]*v1.z + gs[14]*v2.z + gs[15]*v3.z;
    o.w = gs[12]*v0.w + gs[13]*v1.w + gs[14]*v2.w + gs[15]*v3.w;
    __stcs(pout + (BIT_C + BIT_D), o);
}

extern "C" void kernel_launch(void* const* d_in, const int* in_sizes, int n_in,
                              void* d_out, int out_size)
{
    const float4* state = (const float4*)d_in[0];
    const float*  gate  = (const float*)d_in[1];
    float4*       out   = (float4*)d_out;

    const unsigned threads = 256;
    const unsigned blocks  = N_REST / threads;   // 2^22 / 256 = 16384
    quantum_gate2_kernel<<<blocks, threads>>>(state, gate, out);
}